// round 15
// baseline (speedup 1.0000x reference)
#include <cuda_runtime.h>
#include <cuda_fp16.h>
#include <math.h>
#include <stdint.h>

#define NN 50000
#define NE 800000
#define H 128
#define LAY 3
#define NG 512
#define NOUT 10
#define HH (H*H)
#define NB2 ((NN + 255) / 256)          // 196 scan blocks (256 threads each)
#define NWMAT (LAY*4 + 1)
#define STRIDE_H 40                 // halves; 80B rows -> LDSM conflict-free
#define STAGE_A (128*STRIDE_H)      // halves
#define STAGE_B (128*STRIDE_H)      // halves
#define CHUNK_H (STAGE_A + 2*STAGE_B)   // A | B0 | B1
#define NSTAGE 3
#define GEMM_SMEM (NSTAGE*CHUNK_H*2)    // 92160 B

#define GEMM_BLOCKS ((NN + 127) / 128)  // 391
#define HIST_BLOCKS 256
#define SCAT_BLOCKS 512
#define AGG_BLOCKS  (NN/8)              // 6250 (8 warps/block, 1 warp/node)
#define DEGZ_BLOCKS ((NN + 127) / 128)  // 391 (zero deg at graph tail, 128 thr)

// ---------------- scratch (static device globals) ---------------------------
__device__ __half   d_x16[NN*H];
__device__ __half   d_h16A[NN*H];
__device__ __half   d_h16B[NN*H];
__device__ __half   d_s16[NN*H];     // sum
__device__ __half   d_g16[NN*H];     // gcn
__device__ __half   d_Wh[NWMAT*HH];  // fp16 weights, [mat][n][k]
__device__ int      d_deg[NN];       // zero-init at load; re-zeroed at graph tail
__device__ int      d_rowptr[NN+1];
__device__ int      d_cursor[NN];
__device__ int      d_csr[NE];
__device__ float    d_invdeg[NN];
__device__ float    d_invsqrt[NN];
__device__ int      d_gstart[NG+1];
__device__ float    d_gfeat[NG*(LAY+1)*H];
__device__ int      d_btot[NB2];

// ---------------- helpers ----------------------------------------------------
__device__ __forceinline__ void cp16(uint32_t dst, const void* src, int sz) {
    asm volatile("cp.async.ca.shared.global [%0], [%1], 16, %2;"
                 :: "r"(dst), "l"(src), "r"(sz));
}
__device__ __forceinline__ void cp_commit() {
    asm volatile("cp.async.commit_group;");
}
template<int N>
__device__ __forceinline__ void cp_wait() {
    asm volatile("cp.async.wait_group %0;" :: "n"(N));
}

__device__ __forceinline__ void ldsm4(uint32_t& r0, uint32_t& r1, uint32_t& r2, uint32_t& r3,
                                      uint32_t addr) {
    asm volatile("ldmatrix.sync.aligned.m8n8.x4.shared.b16 {%0,%1,%2,%3}, [%4];"
                 : "=r"(r0), "=r"(r1), "=r"(r2), "=r"(r3) : "r"(addr));
}

__device__ __forceinline__ void mma_f16(float* acc,
                                        uint32_t a0, uint32_t a1, uint32_t a2, uint32_t a3,
                                        uint32_t b0, uint32_t b1) {
    asm volatile(
        "mma.sync.aligned.m16n8k16.row.col.f32.f16.f16.f32 "
        "{%0,%1,%2,%3}, {%4,%5,%6,%7}, {%8,%9}, {%0,%1,%2,%3};"
        : "+f"(acc[0]), "+f"(acc[1]), "+f"(acc[2]), "+f"(acc[3])
        : "r"(a0), "r"(a1), "r"(a2), "r"(a3), "r"(b0), "r"(b1));
}

__device__ __forceinline__ uint32_t hmul2u(uint32_t a, uint32_t s) {
    __half2 r = __hmul2(*reinterpret_cast<__half2*>(&a),
                        *reinterpret_cast<__half2*>(&s));
    return *reinterpret_cast<uint32_t*>(&r);
}

// ---------------- readout body (shared) --------------------------------------
__device__ __forceinline__ void readout_body(const __half* __restrict__ h16,
                                             const float* __restrict__ lro,
                                             int layer, int gr, int c) {
    int beg = d_gstart[gr], end = d_gstart[gr+1];
    float s = 0.f, mx = -3.4e38f;
    for (int n = beg; n < end; n++) {
        float v = __half2float(h16[n*H + c]);
        s += v;
        mx = fmaxf(mx, v);
    }
    int cnt = end - beg;
    float mean = s / (float)(cnt > 1 ? cnt : 1);
    if (cnt == 0) mx = 0.f;
    float m = fmaxf(lro[layer*3], fmaxf(lro[layer*3+1], lro[layer*3+2]));
    float e0 = expf(lro[layer*3]-m), e1 = expf(lro[layer*3+1]-m), e2 = expf(lro[layer*3+2]-m);
    float inv = 1.f/(e0+e1+e2);
    d_gfeat[gr*((LAY+1)*H) + layer*H + c] = (e0*mean + e1*mx + e2*s)*inv;
}

// ---------------- scan1 body: 256-elem exclusive scan per block ---------------
__device__ __forceinline__ void scan1_body(const int* __restrict__ in,
                                           int* __restrict__ out, int n, int blk) {
    __shared__ int wsum[8];
    int tid = threadIdx.x;
    int i = blk*256 + tid;
    int lane = tid & 31, warp = tid >> 5;
    int v = (i < n) ? in[i] : 0;
    int x = v;
    #pragma unroll
    for (int o = 1; o < 32; o <<= 1) {
        int y = __shfl_up_sync(0xffffffffu, x, o);
        if (lane >= o) x += y;
    }
    if (lane == 31) wsum[warp] = x;
    __syncthreads();
    if (warp == 0 && lane < 8) {
        int s = wsum[lane];
        #pragma unroll
        for (int o = 1; o < 8; o <<= 1) {
            int y = __shfl_up_sync(0xFFu, s, o);
            if (lane >= o) s += y;
        }
        wsum[lane] = s;
    }
    __syncthreads();
    int incl = x + (warp ? wsum[warp-1] : 0);
    if (i < n) out[i] = incl - v;
    if (tid == 255) d_btot[blk] = incl;
}

// ---------------- GEMM body (mean folded into sum source) --------------------
__device__ __forceinline__ void gemm_body(
    const __half* __restrict__ Ah, const __half* __restrict__ As,
    const __half* __restrict__ Ag, const float* __restrict__ invdeg,
    const __half* __restrict__ Wh, const float* __restrict__ bias,
    __half* __restrict__ out16, int M, int relu, int blk)
{
    extern __shared__ char smem[];
    uint32_t smemAddr = (uint32_t)__cvta_generic_to_shared(smem);

    const __half* srcs[3] = {Ah, As, Ag};
    const int pmat[3] = {0, 2, 3};
    bool layer = (invdeg != nullptr);

    int tid  = threadIdx.x;
    int lane = tid & 31;
    int wid  = tid >> 5;
    int wm = (wid & 3) * 32;
    int wn = (wid >> 2) * 64;
    int lr = lane >> 2, lc = lane & 3;
    int row0 = blk * 128;

    uint32_t aoff = ((wm + (lane & 15)) * STRIDE_H + ((lane >> 4) << 3)) * 2;
    uint32_t boff = ((wn + (lane & 7) + ((lane & 16) >> 1)) * STRIDE_H + (lane & 8)) * 2;

    uint32_t sc[2][2];
    if (layer) {
        #pragma unroll
        for (int mt = 0; mt < 2; mt++) {
            int r0 = row0 + wm + mt*16 + lr;
            int r1 = r0 + 8;
            __half2 h0 = __float2half2_rn((r0 < M) ? invdeg[r0] : 1.f);
            __half2 h1 = __float2half2_rn((r1 < M) ? invdeg[r1] : 1.f);
            sc[mt][0] = *reinterpret_cast<uint32_t*>(&h0);
            sc[mt][1] = *reinterpret_cast<uint32_t*>(&h1);
        }
    }

    float acc[2][8][4];
    #pragma unroll
    for (int mt = 0; mt < 2; mt++)
        #pragma unroll
        for (int nt = 0; nt < 8; nt++)
            #pragma unroll
            for (int c = 0; c < 4; c++) acc[mt][nt][c] = 0.f;

    const int C = layer ? 12 : 4;

    auto issue = [&](int c) {
        int st = c % NSTAGE;
        int src = layer ? (c >> 2) : 0;
        int k0 = (c & 3) * 32;
        uint32_t stBase = smemAddr + st*CHUNK_H*2;
        const __half* A  = srcs[src];
        const __half* Wp = Wh + (layer ? pmat[src] : 0)*HH;
        #pragma unroll
        for (int i = 0; i < 2; i++) {
            int idx = tid + i*256;
            int m = idx >> 2, kg = (idx & 3) * 8;
            int r = row0 + m;
            const __half* sp = A + (size_t)(r < M ? r : 0)*H + k0 + kg;
            cp16(stBase + (m*STRIDE_H + kg)*2, sp, (r < M) ? 16 : 0);
        }
        #pragma unroll
        for (int i = 0; i < 2; i++) {
            int idx = tid + i*256;
            int n = idx >> 2, kg = (idx & 3) * 8;
            cp16(stBase + (STAGE_A + n*STRIDE_H + kg)*2, Wp + n*H + k0 + kg, 16);
        }
        if (layer && src == 1) {
            const __half* Wm = Wh + 1*HH;
            #pragma unroll
            for (int i = 0; i < 2; i++) {
                int idx = tid + i*256;
                int n = idx >> 2, kg = (idx & 3) * 8;
                cp16(stBase + (STAGE_A + STAGE_B + n*STRIDE_H + kg)*2,
                     Wm + n*H + k0 + kg, 16);
            }
        }
        cp_commit();
    };

    issue(0);
    if (C > 1) issue(1);
    for (int c = 0; c < C; c++) {
        if (c < C-1) cp_wait<1>(); else cp_wait<0>();
        __syncthreads();
        if (c + 2 < C) issue(c + 2);

        int st = c % NSTAGE;
        int src = layer ? (c >> 2) : 0;
        bool dual = layer && (src == 1);
        uint32_t stBase = smemAddr + st*CHUNK_H*2;
        uint32_t aBase  = stBase + aoff;
        uint32_t bBase  = stBase + STAGE_A*2 + boff;
        uint32_t b2Base = bBase + STAGE_B*2;

        #pragma unroll
        for (int kb = 0; kb < 32; kb += 16) {
            uint32_t a[2][4];
            #pragma unroll
            for (int mt = 0; mt < 2; mt++)
                ldsm4(a[mt][0], a[mt][1], a[mt][2], a[mt][3],
                      aBase + (mt*16*STRIDE_H + kb)*2);
            uint32_t b[4][4];
            #pragma unroll
            for (int j = 0; j < 4; j++)
                ldsm4(b[j][0], b[j][1], b[j][2], b[j][3],
                      bBase + (j*16*STRIDE_H + kb)*2);
            #pragma unroll
            for (int mt = 0; mt < 2; mt++)
                #pragma unroll
                for (int j = 0; j < 4; j++) {
                    mma_f16(acc[mt][2*j],   a[mt][0], a[mt][1], a[mt][2], a[mt][3],
                            b[j][0], b[j][1]);
                    mma_f16(acc[mt][2*j+1], a[mt][0], a[mt][1], a[mt][2], a[mt][3],
                            b[j][2], b[j][3]);
                }
            if (dual) {
                uint32_t am[2][4];
                #pragma unroll
                for (int mt = 0; mt < 2; mt++) {
                    am[mt][0] = hmul2u(a[mt][0], sc[mt][0]);
                    am[mt][1] = hmul2u(a[mt][1], sc[mt][1]);
                    am[mt][2] = hmul2u(a[mt][2], sc[mt][0]);
                    am[mt][3] = hmul2u(a[mt][3], sc[mt][1]);
                }
                uint32_t bm[4][4];
                #pragma unroll
                for (int j = 0; j < 4; j++)
                    ldsm4(bm[j][0], bm[j][1], bm[j][2], bm[j][3],
                          b2Base + (j*16*STRIDE_H + kb)*2);
                #pragma unroll
                for (int mt = 0; mt < 2; mt++)
                    #pragma unroll
                    for (int j = 0; j < 4; j++) {
                        mma_f16(acc[mt][2*j],   am[mt][0], am[mt][1], am[mt][2], am[mt][3],
                                bm[j][0], bm[j][1]);
                        mma_f16(acc[mt][2*j+1], am[mt][0], am[mt][1], am[mt][2], am[mt][3],
                                bm[j][2], bm[j][3]);
                    }
            }
        }
    }

    #pragma unroll
    for (int mt = 0; mt < 2; mt++) {
        int r0 = row0 + wm + mt*16 + lr;
        int r1 = r0 + 8;
        #pragma unroll
        for (int nt = 0; nt < 8; nt++) {
            int c = wn + nt*8 + 2*lc;
            float b0 = bias ? bias[c]   : 0.f;
            float b1 = bias ? bias[c+1] : 0.f;
            float v0 = acc[mt][nt][0] + b0;
            float v1 = acc[mt][nt][1] + b1;
            float v2 = acc[mt][nt][2] + b0;
            float v3 = acc[mt][nt][3] + b1;
            if (relu) {
                v0 = fmaxf(v0, 0.f); v1 = fmaxf(v1, 0.f);
                v2 = fmaxf(v2, 0.f); v3 = fmaxf(v3, 0.f);
            }
            if (r0 < M)
                *reinterpret_cast<__half2*>(out16 + (size_t)r0*H + c) = __floats2half2_rn(v0, v1);
            if (r1 < M)
                *reinterpret_cast<__half2*>(out16 + (size_t)r1*H + c) = __floats2half2_rn(v2, v3);
        }
    }
}

// ---------------- prep: x->fp16 + weight combine + deg histogram -------------
// d_deg is zero on entry (zero-init at load; re-zeroed at graph tail).
#define TOHALF_B ((NN*H/2 + 255)/256)
#define WCOMB_B ((NWMAT*HH + 255)/256)
__global__ void k_prep(const float* __restrict__ x, const float* __restrict__ Wna,
                       const float* __restrict__ lin1_W, const float* __restrict__ lna,
                       const int* __restrict__ dst) {
    if ((int)blockIdx.x < TOHALF_B) {
        int i = blockIdx.x*blockDim.x + threadIdx.x;
        if (i < NN*H/2) {
            float2 v = reinterpret_cast<const float2*>(x)[i];
            reinterpret_cast<__half2*>(d_x16)[i] = __floats2half2_rn(v.x, v.y);
        }
    } else if ((int)blockIdx.x < TOHALF_B + WCOMB_B) {
        int i = (blockIdx.x - TOHALF_B)*blockDim.x + threadIdx.x;
        if (i >= NWMAT*HH) return;
        int mat = i/HH; int e = i%HH;
        int k = e >> 7, n = e & 127;
        float v;
        if (mat < LAY*4) {
            int l = mat >> 2, s = mat & 3;
            float m = -1e30f;
            #pragma unroll
            for (int j = 0; j < 4; j++) m = fmaxf(m, lna[l*4+j]);
            float ex[4]; float sum = 0.f;
            #pragma unroll
            for (int j = 0; j < 4; j++) { ex[j] = expf(lna[l*4+j]-m); sum += ex[j]; }
            float na0 = ex[0]/sum, na1 = ex[1]/sum, na2 = ex[2]/sum, na3 = ex[3]/sum;
            const float* W = Wna + l*5*HH;
            int idx = k*H + n;
            if (s == 0)      v = na1*W[1*HH+idx] + na2*W[3*HH+idx] + na3*W[4*HH+idx];
            else if (s == 1) v = na1*W[2*HH+idx];
            else if (s == 2) v = na2*W[3*HH+idx];
            else             v = na0*W[0*HH+idx];
        } else {
            v = lin1_W[k*H + n];
        }
        d_Wh[mat*HH + n*H + k] = __float2half(v);
    } else {
        int i = (blockIdx.x - TOHALF_B - WCOMB_B)*blockDim.x + threadIdx.x;
        int stride = HIST_BLOCKS*blockDim.x;
        const int4* d4 = reinterpret_cast<const int4*>(dst);
        for (int e = i; e < NE/4; e += stride) {
            int4 v = d4[e];
            atomicAdd(&d_deg[v.x], 1);
            atomicAdd(&d_deg[v.y], 1);
            atomicAdd(&d_deg[v.z], 1);
            atomicAdd(&d_deg[v.w], 1);
        }
    }
}

// ---------------- merged: lin1 GEMM + scan phase 1 ---------------------------
__global__ void __launch_bounds__(256)
k_gemm_scan1(const __half* __restrict__ x16, const __half* __restrict__ Wh,
             const float* __restrict__ bias, __half* __restrict__ out16) {
    if ((int)blockIdx.x < GEMM_BLOCKS) {
        gemm_body(x16, x16, x16, nullptr, Wh, bias, out16, NN, 0, blockIdx.x);
    } else {
        scan1_body(d_deg, d_rowptr, NN, blockIdx.x - GEMM_BLOCKS);
    }
}

// ---- scan phase 2: carry (via shared) + cursor/stats + gstart ---------------
__global__ void k_scan3c(int* __restrict__ out, int n, const int* __restrict__ batch) {
    __shared__ int sb[NB2];
    __shared__ int s_carry;
    int tid = threadIdx.x;
    for (int t = tid; t < NB2; t += 256) sb[t] = d_btot[t];
    __syncthreads();
    if (tid == 0) {
        int c = 0;
        for (int b = 0; b < (int)blockIdx.x; b++) c += sb[b];
        s_carry = c;
        if (blockIdx.x == 0) {
            int tot = 0;
            for (int b = 0; b < NB2; b++) tot += sb[b];
            out[n] = tot;
        }
    }
    __syncthreads();
    int carry = s_carry;
    int i = blockIdx.x*256 + tid;
    if (i < n) {
        int v = out[i] + carry;
        out[i] = v;
        d_cursor[i] = v;
        int c = d_deg[i];
        float m = (float)(c > 1 ? c : 1);
        d_invdeg[i]  = 1.0f/m;
        d_invsqrt[i] = rsqrtf(m);
    }
    int g = blockIdx.x*256 + tid;
    if (g <= NG) {
        if (g == NG) d_gstart[NG] = NN;
        else {
            int lo = 0, hi = NN;
            while (lo < hi) {
                int mid = (lo + hi) >> 1;
                if (batch[mid] < g) lo = mid + 1; else hi = mid;
            }
            d_gstart[g] = lo;
        }
    }
}

// ---------------- merged: CSR scatter + readout layer 0 ----------------------
__global__ void k_scatter_read0(const int* __restrict__ src, const int* __restrict__ dst,
                                const __half* __restrict__ h16,
                                const float* __restrict__ lro) {
    if ((int)blockIdx.x < SCAT_BLOCKS) {
        int i = blockIdx.x*blockDim.x + threadIdx.x;
        int stride = SCAT_BLOCKS*blockDim.x;
        const int4* s4 = reinterpret_cast<const int4*>(src);
        const int4* d4 = reinterpret_cast<const int4*>(dst);
        for (int e = i; e < NE/4; e += stride) {
            int4 sv = s4[e];
            int4 dv = d4[e];
            d_csr[atomicAdd(&d_cursor[dv.x], 1)] = sv.x;
            d_csr[atomicAdd(&d_cursor[dv.y], 1)] = sv.y;
            d_csr[atomicAdd(&d_cursor[dv.z], 1)] = sv.z;
            d_csr[atomicAdd(&d_cursor[dv.w], 1)] = sv.w;
        }
    } else {
        int gr = blockIdx.x - SCAT_BLOCKS;
        if (threadIdx.x < H) readout_body(h16, lro, 0, gr, threadIdx.x);
    }
}

// ---------------- merged: aggregation + readout(layer) -----------------------
__global__ void k_agg_read(const __half* __restrict__ h16, const float* __restrict__ lro,
                           int layer, int doread) {
    if ((int)blockIdx.x < AGG_BLOCKS) {
        int gw   = (blockIdx.x*blockDim.x + threadIdx.x) >> 5;
        int lane = threadIdx.x & 31;
        if (gw >= NN) return;
        int beg = d_rowptr[gw], end = d_rowptr[gw+1];
        const uint2* h2 = reinterpret_cast<const uint2*>(h16);
        float4 s = {0.f,0.f,0.f,0.f};
        float4 g = {0.f,0.f,0.f,0.f};
        for (int e = beg; e < end; e++) {
            int src  = d_csr[e];
            float is = d_invsqrt[src];
            uint2 raw = h2[src*32 + lane];
            float2 lo = __half22float2(*reinterpret_cast<const __half2*>(&raw.x));
            float2 hi = __half22float2(*reinterpret_cast<const __half2*>(&raw.y));
            s.x += lo.x;    s.y += lo.y;    s.z += hi.x;    s.w += hi.y;
            g.x += lo.x*is; g.y += lo.y*is; g.z += hi.x*is; g.w += hi.y*is;
        }
        float isd = d_invsqrt[gw];
        int o = gw*32 + lane;
        uint2 su, gu;
        *reinterpret_cast<__half2*>(&su.x) = __floats2half2_rn(s.x, s.y);
        *reinterpret_cast<__half2*>(&su.y) = __floats2half2_rn(s.z, s.w);
        *reinterpret_cast<__half2*>(&gu.x) = __floats2half2_rn(g.x*isd, g.y*isd);
        *reinterpret_cast<__half2*>(&gu.y) = __floats2half2_rn(g.z*isd, g.w*isd);
        reinterpret_cast<uint2*>(d_s16)[o] = su;
        reinterpret_cast<uint2*>(d_g16)[o] = gu;
    } else if (doread) {
        int gr = blockIdx.x - AGG_BLOCKS;
        if (threadIdx.x < H) readout_body(h16, lro, layer, gr, threadIdx.x);
    }
}

// ---------------- layer GEMM wrapper -----------------------------------------
__global__ void __launch_bounds__(256)
k_gemm_layer(const __half* __restrict__ Ah, const __half* __restrict__ As,
             const __half* __restrict__ Ag, const float* __restrict__ invdeg,
             const __half* __restrict__ Wh, __half* __restrict__ out16) {
    gemm_body(Ah, As, Ag, invdeg, Wh, nullptr, out16, NN, 1, blockIdx.x);
}

// ---------------- head (fused final readout) + deg re-zero tail --------------
__global__ void k_head(const __half* __restrict__ hlast, const float* __restrict__ lro,
                       const float* __restrict__ Wl, const float* __restrict__ bl,
                       const float* __restrict__ Wc, const float* __restrict__ bc,
                       float* __restrict__ out) {
    if ((int)blockIdx.x >= NG) {
        int i = (blockIdx.x - NG)*blockDim.x + threadIdx.x;
        if (i < NN) d_deg[i] = 0;
        return;
    }
    __shared__ float sg[(LAY+1)*H];
    __shared__ float mid[H];
    int gr = blockIdx.x;
    int t  = threadIdx.x;
    readout_body(hlast, lro, LAY, gr, t);
    __syncthreads();
    for (int i = t; i < (LAY+1)*H; i += H) sg[i] = d_gfeat[gr*((LAY+1)*H) + i];
    __syncthreads();
    float acc = bl[t];
    for (int k = 0; k < (LAY+1)*H; k++) acc += sg[k]*Wl[k*H + t];
    mid[t] = fmaxf(acc, 0.f);
    __syncthreads();
    if (t < NOUT) {
        float a = bc[t];
        for (int k = 0; k < H; k++) a += mid[k]*Wc[k*NOUT + t];
        out[gr*NOUT + t] = a;
    }
}

// ---------------- launch ----------------------------------------------------
extern "C" void kernel_launch(void* const* d_in, const int* in_sizes, int n_in,
                              void* d_out, int out_size) {
    const float* x      = (const float*)d_in[0];
    const int*   ei     = (const int*)  d_in[1];
    const int*   batch  = (const int*)  d_in[2];
    const float* lin1_W = (const float*)d_in[3];
    const float* lin1_b = (const float*)d_in[4];
    const float* Wna    = (const float*)d_in[5];
    const float* lna    = (const float*)d_in[6];
    const float* lro    = (const float*)d_in[7];
    const float* lout_W = (const float*)d_in[8];
    const float* lout_b = (const float*)d_in[9];
    const float* cls_W  = (const float*)d_in[10];
    const float* cls_b  = (const float*)d_in[11];
    const int* srcp = ei;
    const int* dstp = ei + NE;

    __half *x16, *h16A, *h16B, *s16, *g16, *pWh;
    float *pinvdeg;
    int *prowptr;
    cudaGetSymbolAddress((void**)&x16,     d_x16);
    cudaGetSymbolAddress((void**)&h16A,    d_h16A);
    cudaGetSymbolAddress((void**)&h16B,    d_h16B);
    cudaGetSymbolAddress((void**)&s16,     d_s16);
    cudaGetSymbolAddress((void**)&g16,     d_g16);
    cudaGetSymbolAddress((void**)&pWh,     d_Wh);
    cudaGetSymbolAddress((void**)&pinvdeg, d_invdeg);
    cudaGetSymbolAddress((void**)&prowptr, d_rowptr);

    cudaFuncSetAttribute(k_gemm_scan1,
                         cudaFuncAttributeMaxDynamicSharedMemorySize, GEMM_SMEM);
    cudaFuncSetAttribute(k_gemm_layer,
                         cudaFuncAttributeMaxDynamicSharedMemorySize, GEMM_SMEM);

    k_prep<<<TOHALF_B + WCOMB_B + HIST_BLOCKS, 256>>>(x, Wna, lin1_W, lna, dstp);
    k_gemm_scan1<<<GEMM_BLOCKS + NB2, 256, GEMM_SMEM>>>(
        x16, pWh + (LAY*4)*HH, lin1_b, h16A);
    k_scan3c<<<NB2, 256>>>(prowptr, NN, batch);
    k_scatter_read0<<<SCAT_BLOCKS + NG, 256>>>(srcp, dstp, h16A, lro);

    __half* cur16 = h16A;
    __half* nxt16 = h16B;
    for (int l = 0; l < LAY; l++) {
        k_agg_read<<<AGG_BLOCKS + NG, 256>>>(cur16, lro, l, l > 0);
        k_gemm_layer<<<GEMM_BLOCKS, 256, GEMM_SMEM>>>(cur16, s16, g16, pinvdeg,
                                                      pWh + l*4*HH, nxt16);
        __half* t16 = cur16; cur16 = nxt16; nxt16 = t16;
    }
    k_head<<<NG + DEGZ_BLOCKS, H>>>(cur16, lro, lout_W, lout_b, cls_W, cls_b,
                                    (float*)d_out);
}

// round 17
// speedup vs baseline: 1.0213x; 1.0213x over previous
#include <cuda_runtime.h>
#include <cuda_fp16.h>
#include <math.h>
#include <stdint.h>

#define NN 50000
#define NE 800000
#define H 128
#define LAY 3
#define NG 512
#define NOUT 10
#define HH (H*H)
#define NB2 ((NN + 255) / 256)          // 196 scan blocks
#define NWMAT (LAY*4 + 1)
#define STRIDE_H 40                 // halves; 80B rows -> LDSM conflict-free
#define STAGE_A (128*STRIDE_H)
#define STAGE_B (128*STRIDE_H)
#define CHUNK_H (STAGE_A + 2*STAGE_B)
#define NSTAGE 3
#define GEMM_SMEM (NSTAGE*CHUNK_H*2)    // 92160 B

#define GEMM_BLOCKS ((NN + 127) / 128)  // 391
#define HIST_BLOCKS 256
#define SCAT_BLOCKS 768
#define AGG_BLOCKS  (NN/8)              // 6250
#define DEGZ_BLOCKS ((NN + 127) / 128)

// ---------------- scratch (static device globals) ---------------------------
__device__ __half   d_x16[NN*H];
__device__ __half   d_h16A[NN*H];
__device__ __half   d_h16B[NN*H];
__device__ __half   d_s16[NN*H];
__device__ __half   d_g16[NN*H];
__device__ __half   d_Wh[NWMAT*HH];
__device__ int      d_deg[NN];       // zero-init at load; re-zeroed at graph tail
__device__ int      d_rowptr[NN+1];
__device__ int      d_cursor[NN];
__device__ int      d_csr[NE];
__device__ float    d_invdeg[NN];
__device__ float    d_invsqrt[NN];
__device__ int      d_gstart[NG+1];
__device__ float    d_gfeat[NG*(LAY+1)*H];

// ---------------- helpers ----------------------------------------------------
__device__ __forceinline__ void cp16(uint32_t dst, const void* src, int sz) {
    asm volatile("cp.async.ca.shared.global [%0], [%1], 16, %2;"
                 :: "r"(dst), "l"(src), "r"(sz));
}
__device__ __forceinline__ void cp_commit() {
    asm volatile("cp.async.commit_group;");
}
template<int N>
__device__ __forceinline__ void cp_wait() {
    asm volatile("cp.async.wait_group %0;" :: "n"(N));
}

__device__ __forceinline__ void ldsm4(uint32_t& r0, uint32_t& r1, uint32_t& r2, uint32_t& r3,
                                      uint32_t addr) {
    asm volatile("ldmatrix.sync.aligned.m8n8.x4.shared.b16 {%0,%1,%2,%3}, [%4];"
                 : "=r"(r0), "=r"(r1), "=r"(r2), "=r"(r3) : "r"(addr));
}

__device__ __forceinline__ void mma_f16(float* acc,
                                        uint32_t a0, uint32_t a1, uint32_t a2, uint32_t a3,
                                        uint32_t b0, uint32_t b1) {
    asm volatile(
        "mma.sync.aligned.m16n8k16.row.col.f32.f16.f16.f32 "
        "{%0,%1,%2,%3}, {%4,%5,%6,%7}, {%8,%9}, {%0,%1,%2,%3};"
        : "+f"(acc[0]), "+f"(acc[1]), "+f"(acc[2]), "+f"(acc[3])
        : "r"(a0), "r"(a1), "r"(a2), "r"(a3), "r"(b0), "r"(b1));
}

__device__ __forceinline__ uint32_t hmul2u(uint32_t a, uint32_t s) {
    __half2 r = __hmul2(*reinterpret_cast<__half2*>(&a),
                        *reinterpret_cast<__half2*>(&s));
    return *reinterpret_cast<uint32_t*>(&r);
}

// ---------------- readout body ------------------------------------------------
__device__ __forceinline__ void readout_body(const __half* __restrict__ h16,
                                             const float* __restrict__ lro,
                                             int layer, int gr, int c) {
    int beg = d_gstart[gr], end = d_gstart[gr+1];
    float s = 0.f, mx = -3.4e38f;
    for (int n = beg; n < end; n++) {
        float v = __half2float(h16[n*H + c]);
        s += v;
        mx = fmaxf(mx, v);
    }
    int cnt = end - beg;
    float mean = s / (float)(cnt > 1 ? cnt : 1);
    if (cnt == 0) mx = 0.f;
    float m = fmaxf(lro[layer*3], fmaxf(lro[layer*3+1], lro[layer*3+2]));
    float e0 = expf(lro[layer*3]-m), e1 = expf(lro[layer*3+1]-m), e2 = expf(lro[layer*3+2]-m);
    float inv = 1.f/(e0+e1+e2);
    d_gfeat[gr*((LAY+1)*H) + layer*H + c] = (e0*mean + e1*mx + e2*s)*inv;
}

// ---------------- GEMM body (mean folded into sum source) --------------------
__device__ __forceinline__ void gemm_body(
    const __half* __restrict__ Ah, const __half* __restrict__ As,
    const __half* __restrict__ Ag, const float* __restrict__ invdeg,
    const __half* __restrict__ Wh, const float* __restrict__ bias,
    __half* __restrict__ out16, int M, int relu, int blk)
{
    extern __shared__ char smem[];
    uint32_t smemAddr = (uint32_t)__cvta_generic_to_shared(smem);

    const __half* srcs[3] = {Ah, As, Ag};
    const int pmat[3] = {0, 2, 3};
    bool layer = (invdeg != nullptr);

    int tid  = threadIdx.x;
    int lane = tid & 31;
    int wid  = tid >> 5;
    int wm = (wid & 3) * 32;
    int wn = (wid >> 2) * 64;
    int lr = lane >> 2, lc = lane & 3;
    int row0 = blk * 128;

    uint32_t aoff = ((wm + (lane & 15)) * STRIDE_H + ((lane >> 4) << 3)) * 2;
    uint32_t boff = ((wn + (lane & 7) + ((lane & 16) >> 1)) * STRIDE_H + (lane & 8)) * 2;

    uint32_t sc[2][2];
    if (layer) {
        #pragma unroll
        for (int mt = 0; mt < 2; mt++) {
            int r0 = row0 + wm + mt*16 + lr;
            int r1 = r0 + 8;
            __half2 h0 = __float2half2_rn((r0 < M) ? invdeg[r0] : 1.f);
            __half2 h1 = __float2half2_rn((r1 < M) ? invdeg[r1] : 1.f);
            sc[mt][0] = *reinterpret_cast<uint32_t*>(&h0);
            sc[mt][1] = *reinterpret_cast<uint32_t*>(&h1);
        }
    }

    float acc[2][8][4];
    #pragma unroll
    for (int mt = 0; mt < 2; mt++)
        #pragma unroll
        for (int nt = 0; nt < 8; nt++)
            #pragma unroll
            for (int c = 0; c < 4; c++) acc[mt][nt][c] = 0.f;

    const int C = layer ? 12 : 4;

    auto issue = [&](int c) {
        int st = c % NSTAGE;
        int src = layer ? (c >> 2) : 0;
        int k0 = (c & 3) * 32;
        uint32_t stBase = smemAddr + st*CHUNK_H*2;
        const __half* A  = srcs[src];
        const __half* Wp = Wh + (layer ? pmat[src] : 0)*HH;
        #pragma unroll
        for (int i = 0; i < 2; i++) {
            int idx = tid + i*256;
            int m = idx >> 2, kg = (idx & 3) * 8;
            int r = row0 + m;
            const __half* sp = A + (size_t)(r < M ? r : 0)*H + k0 + kg;
            cp16(stBase + (m*STRIDE_H + kg)*2, sp, (r < M) ? 16 : 0);
        }
        #pragma unroll
        for (int i = 0; i < 2; i++) {
            int idx = tid + i*256;
            int n = idx >> 2, kg = (idx & 3) * 8;
            cp16(stBase + (STAGE_A + n*STRIDE_H + kg)*2, Wp + n*H + k0 + kg, 16);
        }
        if (layer && src == 1) {
            const __half* Wm = Wh + 1*HH;
            #pragma unroll
            for (int i = 0; i < 2; i++) {
                int idx = tid + i*256;
                int n = idx >> 2, kg = (idx & 3) * 8;
                cp16(stBase + (STAGE_A + STAGE_B + n*STRIDE_H + kg)*2,
                     Wm + n*H + k0 + kg, 16);
            }
        }
        cp_commit();
    };

    issue(0);
    if (C > 1) issue(1);
    for (int c = 0; c < C; c++) {
        if (c < C-1) cp_wait<1>(); else cp_wait<0>();
        __syncthreads();
        if (c + 2 < C) issue(c + 2);

        int st = c % NSTAGE;
        int src = layer ? (c >> 2) : 0;
        bool dual = layer && (src == 1);
        uint32_t stBase = smemAddr + st*CHUNK_H*2;
        uint32_t aBase  = stBase + aoff;
        uint32_t bBase  = stBase + STAGE_A*2 + boff;
        uint32_t b2Base = bBase + STAGE_B*2;

        #pragma unroll
        for (int kb = 0; kb < 32; kb += 16) {
            uint32_t a[2][4];
            #pragma unroll
            for (int mt = 0; mt < 2; mt++)
                ldsm4(a[mt][0], a[mt][1], a[mt][2], a[mt][3],
                      aBase + (mt*16*STRIDE_H + kb)*2);
            uint32_t b[4][4];
            #pragma unroll
            for (int j = 0; j < 4; j++)
                ldsm4(b[j][0], b[j][1], b[j][2], b[j][3],
                      bBase + (j*16*STRIDE_H + kb)*2);
            #pragma unroll
            for (int mt = 0; mt < 2; mt++)
                #pragma unroll
                for (int j = 0; j < 4; j++) {
                    mma_f16(acc[mt][2*j],   a[mt][0], a[mt][1], a[mt][2], a[mt][3],
                            b[j][0], b[j][1]);
                    mma_f16(acc[mt][2*j+1], a[mt][0], a[mt][1], a[mt][2], a[mt][3],
                            b[j][2], b[j][3]);
                }
            if (dual) {
                uint32_t am[2][4];
                #pragma unroll
                for (int mt = 0; mt < 2; mt++) {
                    am[mt][0] = hmul2u(a[mt][0], sc[mt][0]);
                    am[mt][1] = hmul2u(a[mt][1], sc[mt][1]);
                    am[mt][2] = hmul2u(a[mt][2], sc[mt][0]);
                    am[mt][3] = hmul2u(a[mt][3], sc[mt][1]);
                }
                uint32_t bm[4][4];
                #pragma unroll
                for (int j = 0; j < 4; j++)
                    ldsm4(bm[j][0], bm[j][1], bm[j][2], bm[j][3],
                          b2Base + (j*16*STRIDE_H + kb)*2);
                #pragma unroll
                for (int mt = 0; mt < 2; mt++)
                    #pragma unroll
                    for (int j = 0; j < 4; j++) {
                        mma_f16(acc[mt][2*j],   am[mt][0], am[mt][1], am[mt][2], am[mt][3],
                                bm[j][0], bm[j][1]);
                        mma_f16(acc[mt][2*j+1], am[mt][0], am[mt][1], am[mt][2], am[mt][3],
                                bm[j][2], bm[j][3]);
                    }
            }
        }
    }

    #pragma unroll
    for (int mt = 0; mt < 2; mt++) {
        int r0 = row0 + wm + mt*16 + lr;
        int r1 = r0 + 8;
        #pragma unroll
        for (int nt = 0; nt < 8; nt++) {
            int c = wn + nt*8 + 2*lc;
            float b0 = bias ? bias[c]   : 0.f;
            float b1 = bias ? bias[c+1] : 0.f;
            float v0 = acc[mt][nt][0] + b0;
            float v1 = acc[mt][nt][1] + b1;
            float v2 = acc[mt][nt][2] + b0;
            float v3 = acc[mt][nt][3] + b1;
            if (relu) {
                v0 = fmaxf(v0, 0.f); v1 = fmaxf(v1, 0.f);
                v2 = fmaxf(v2, 0.f); v3 = fmaxf(v3, 0.f);
            }
            if (r0 < M)
                *reinterpret_cast<__half2*>(out16 + (size_t)r0*H + c) = __floats2half2_rn(v0, v1);
            if (r1 < M)
                *reinterpret_cast<__half2*>(out16 + (size_t)r1*H + c) = __floats2half2_rn(v2, v3);
        }
    }
}

// ---------------- prep: x->fp16 + weight combine + deg histogram -------------
#define TOHALF_B ((NN*H/2 + 255)/256)
#define WCOMB_B ((NWMAT*HH + 255)/256)
__global__ void k_prep(const float* __restrict__ x, const float* __restrict__ Wna,
                       const float* __restrict__ lin1_W, const float* __restrict__ lna,
                       const int* __restrict__ dst) {
    if ((int)blockIdx.x < TOHALF_B) {
        int i = blockIdx.x*blockDim.x + threadIdx.x;
        if (i < NN*H/2) {
            float2 v = reinterpret_cast<const float2*>(x)[i];
            reinterpret_cast<__half2*>(d_x16)[i] = __floats2half2_rn(v.x, v.y);
        }
    } else if ((int)blockIdx.x < TOHALF_B + WCOMB_B) {
        int i = (blockIdx.x - TOHALF_B)*blockDim.x + threadIdx.x;
        if (i >= NWMAT*HH) return;
        int mat = i/HH; int e = i%HH;
        int k = e >> 7, n = e & 127;
        float v;
        if (mat < LAY*4) {
            int l = mat >> 2, s = mat & 3;
            float m = -1e30f;
            #pragma unroll
            for (int j = 0; j < 4; j++) m = fmaxf(m, lna[l*4+j]);
            float ex[4]; float sum = 0.f;
            #pragma unroll
            for (int j = 0; j < 4; j++) { ex[j] = expf(lna[l*4+j]-m); sum += ex[j]; }
            float na0 = ex[0]/sum, na1 = ex[1]/sum, na2 = ex[2]/sum, na3 = ex[3]/sum;
            const float* W = Wna + l*5*HH;
            int idx = k*H + n;
            if (s == 0)      v = na1*W[1*HH+idx] + na2*W[3*HH+idx] + na3*W[4*HH+idx];
            else if (s == 1) v = na1*W[2*HH+idx];
            else if (s == 2) v = na2*W[3*HH+idx];
            else             v = na0*W[0*HH+idx];
        } else {
            v = lin1_W[k*H + n];
        }
        d_Wh[mat*HH + n*H + k] = __float2half(v);
    } else {
        int i = (blockIdx.x - TOHALF_B - WCOMB_B)*blockDim.x + threadIdx.x;
        int stride = HIST_BLOCKS*blockDim.x;
        const int4* d4 = reinterpret_cast<const int4*>(dst);
        for (int e = i; e < NE/4; e += stride) {
            int4 v = d4[e];
            atomicAdd(&d_deg[v.x], 1);
            atomicAdd(&d_deg[v.y], 1);
            atomicAdd(&d_deg[v.z], 1);
            atomicAdd(&d_deg[v.w], 1);
        }
    }
}

// ---- fused scan: per-block brute-force carry + tile scan + stats + gstart ---
__global__ void k_scan(int* __restrict__ rowptr, const int* __restrict__ batch) {
    __shared__ int red[256];
    __shared__ int wsum[8];
    int b = blockIdx.x, tid = threadIdx.x;
    int base = b * 256;

    // carry = sum deg[0..base)
    int acc = 0;
    for (int i = tid; i < base; i += 256) acc += d_deg[i];
    red[tid] = acc;
    __syncthreads();
    #pragma unroll
    for (int o = 128; o > 0; o >>= 1) {
        if (tid < o) red[tid] += red[tid + o];
        __syncthreads();
    }
    int carry = red[0];

    // tile exclusive scan
    int i = base + tid;
    int lane = tid & 31, warp = tid >> 5;
    int v = (i < NN) ? d_deg[i] : 0;
    int x = v;
    #pragma unroll
    for (int o = 1; o < 32; o <<= 1) {
        int y = __shfl_up_sync(0xffffffffu, x, o);
        if (lane >= o) x += y;
    }
    if (lane == 31) wsum[warp] = x;
    __syncthreads();
    if (warp == 0 && lane < 8) {
        int s = wsum[lane];
        #pragma unroll
        for (int o = 1; o < 8; o <<= 1) {
            int y = __shfl_up_sync(0xFFu, s, o);
            if (lane >= o) s += y;
        }
        wsum[lane] = s;
    }
    __syncthreads();
    int excl = x - v + (warp ? wsum[warp-1] : 0);
    if (i < NN) {
        int val = carry + excl;
        rowptr[i] = val;
        d_cursor[i] = val;
        int c = v;
        float m = (float)(c > 1 ? c : 1);
        d_invdeg[i]  = 1.0f/m;
        d_invsqrt[i] = rsqrtf(m);
        if (i == NN-1) rowptr[NN] = val + v;
    }

    // gstart via binary search (batch sorted)
    int g = base + tid;
    if (g <= NG) {
        if (g == NG) d_gstart[NG] = NN;
        else {
            int lo = 0, hi = NN;
            while (lo < hi) {
                int mid = (lo + hi) >> 1;
                if (batch[mid] < g) lo = mid + 1; else hi = mid;
            }
            d_gstart[g] = lo;
        }
    }
}

// ---------------- merged: lin1 GEMM + CSR scatter -----------------------------
__global__ void __launch_bounds__(256)
k_gemm_scat(const __half* __restrict__ x16, const __half* __restrict__ Wh,
            const float* __restrict__ bias, __half* __restrict__ out16,
            const int* __restrict__ src, const int* __restrict__ dst) {
    if ((int)blockIdx.x < GEMM_BLOCKS) {
        gemm_body(x16, x16, x16, nullptr, Wh, bias, out16, NN, 0, blockIdx.x);
    } else {
        int i = (blockIdx.x - GEMM_BLOCKS)*blockDim.x + threadIdx.x;
        int stride = SCAT_BLOCKS*blockDim.x;
        const int4* s4 = reinterpret_cast<const int4*>(src);
        const int4* d4 = reinterpret_cast<const int4*>(dst);
        for (int e = i; e < NE/4; e += stride) {
            int4 sv = s4[e];
            int4 dv = d4[e];
            d_csr[atomicAdd(&d_cursor[dv.x], 1)] = sv.x;
            d_csr[atomicAdd(&d_cursor[dv.y], 1)] = sv.y;
            d_csr[atomicAdd(&d_cursor[dv.z], 1)] = sv.z;
            d_csr[atomicAdd(&d_cursor[dv.w], 1)] = sv.w;
        }
    }
}

// ---------------- merged: aggregation + readout(layer) -----------------------
__global__ void k_agg_read(const __half* __restrict__ h16, const float* __restrict__ lro,
                           int layer) {
    if ((int)blockIdx.x < AGG_BLOCKS) {
        int gw   = (blockIdx.x*blockDim.x + threadIdx.x) >> 5;
        int lane = threadIdx.x & 31;
        if (gw >= NN) return;
        int beg = d_rowptr[gw], end = d_rowptr[gw+1];
        const uint2* h2 = reinterpret_cast<const uint2*>(h16);
        float4 s = {0.f,0.f,0.f,0.f};
        float4 g = {0.f,0.f,0.f,0.f};
        for (int e = beg; e < end; e++) {
            int src  = d_csr[e];
            float is = d_invsqrt[src];
            uint2 raw = h2[src*32 + lane];
            float2 lo = __half22float2(*reinterpret_cast<const __half2*>(&raw.x));
            float2 hi = __half22float2(*reinterpret_cast<const __half2*>(&raw.y));
            s.x += lo.x;    s.y += lo.y;    s.z += hi.x;    s.w += hi.y;
            g.x += lo.x*is; g.y += lo.y*is; g.z += hi.x*is; g.w += hi.y*is;
        }
        float isd = d_invsqrt[gw];
        int o = gw*32 + lane;
        uint2 su, gu;
        *reinterpret_cast<__half2*>(&su.x) = __floats2half2_rn(s.x, s.y);
        *reinterpret_cast<__half2*>(&su.y) = __floats2half2_rn(s.z, s.w);
        *reinterpret_cast<__half2*>(&gu.x) = __floats2half2_rn(g.x*isd, g.y*isd);
        *reinterpret_cast<__half2*>(&gu.y) = __floats2half2_rn(g.z*isd, g.w*isd);
        reinterpret_cast<uint2*>(d_s16)[o] = su;
        reinterpret_cast<uint2*>(d_g16)[o] = gu;
    } else {
        int gr = blockIdx.x - AGG_BLOCKS;
        if (threadIdx.x < H) readout_body(h16, lro, layer, gr, threadIdx.x);
    }
}

// ---------------- layer GEMM wrapper -----------------------------------------
__global__ void __launch_bounds__(256)
k_gemm_layer(const __half* __restrict__ Ah, const __half* __restrict__ As,
             const __half* __restrict__ Ag, const float* __restrict__ invdeg,
             const __half* __restrict__ Wh, __half* __restrict__ out16) {
    gemm_body(Ah, As, Ag, invdeg, Wh, nullptr, out16, NN, 1, blockIdx.x);
}

// ---------------- head (fused final readout) + deg re-zero tail --------------
__global__ void k_head(const __half* __restrict__ hlast, const float* __restrict__ lro,
                       const float* __restrict__ Wl, const float* __restrict__ bl,
                       const float* __restrict__ Wc, const float* __restrict__ bc,
                       float* __restrict__ out) {
    if ((int)blockIdx.x >= NG) {
        int i = (blockIdx.x - NG)*blockDim.x + threadIdx.x;
        if (i < NN) d_deg[i] = 0;
        return;
    }
    __shared__ float sg[(LAY+1)*H];
    __shared__ float mid[H];
    int gr = blockIdx.x;
    int t  = threadIdx.x;
    readout_body(hlast, lro, LAY, gr, t);
    __syncthreads();
    for (int i = t; i < (LAY+1)*H; i += H) sg[i] = d_gfeat[gr*((LAY+1)*H) + i];
    __syncthreads();
    float acc = bl[t];
    for (int k = 0; k < (LAY+1)*H; k++) acc += sg[k]*Wl[k*H + t];
    mid[t] = fmaxf(acc, 0.f);
    __syncthreads();
    if (t < NOUT) {
        float a = bc[t];
        for (int k = 0; k < H; k++) a += mid[k]*Wc[k*NOUT + t];
        out[gr*NOUT + t] = a;
    }
}

// ---------------- launch ----------------------------------------------------
extern "C" void kernel_launch(void* const* d_in, const int* in_sizes, int n_in,
                              void* d_out, int out_size) {
    const float* x      = (const float*)d_in[0];
    const int*   ei     = (const int*)  d_in[1];
    const int*   batch  = (const int*)  d_in[2];
    const float* lin1_W = (const float*)d_in[3];
    const float* lin1_b = (const float*)d_in[4];
    const float* Wna    = (const float*)d_in[5];
    const float* lna    = (const float*)d_in[6];
    const float* lro    = (const float*)d_in[7];
    const float* lout_W = (const float*)d_in[8];
    const float* lout_b = (const float*)d_in[9];
    const float* cls_W  = (const float*)d_in[10];
    const float* cls_b  = (const float*)d_in[11];
    const int* srcp = ei;
    const int* dstp = ei + NE;

    __half *x16, *h16A, *h16B, *s16, *g16, *pWh;
    float *pinvdeg;
    int *prowptr;
    cudaGetSymbolAddress((void**)&x16,     d_x16);
    cudaGetSymbolAddress((void**)&h16A,    d_h16A);
    cudaGetSymbolAddress((void**)&h16B,    d_h16B);
    cudaGetSymbolAddress((void**)&s16,     d_s16);
    cudaGetSymbolAddress((void**)&g16,     d_g16);
    cudaGetSymbolAddress((void**)&pWh,     d_Wh);
    cudaGetSymbolAddress((void**)&pinvdeg, d_invdeg);
    cudaGetSymbolAddress((void**)&prowptr, d_rowptr);

    cudaFuncSetAttribute(k_gemm_scat,
                         cudaFuncAttributeMaxDynamicSharedMemorySize, GEMM_SMEM);
    cudaFuncSetAttribute(k_gemm_layer,
                         cudaFuncAttributeMaxDynamicSharedMemorySize, GEMM_SMEM);

    k_prep<<<TOHALF_B + WCOMB_B + HIST_BLOCKS, 256>>>(x, Wna, lin1_W, lna, dstp);
    k_scan<<<NB2, 256>>>(prowptr, batch);
    k_gemm_scat<<<GEMM_BLOCKS + SCAT_BLOCKS, 256, GEMM_SMEM>>>(
        x16, pWh + (LAY*4)*HH, lin1_b, h16A, srcp, dstp);

    __half* cur16 = h16A;
    __half* nxt16 = h16B;
    for (int l = 0; l < LAY; l++) {
        k_agg_read<<<AGG_BLOCKS + NG, 256>>>(cur16, lro, l);
        k_gemm_layer<<<GEMM_BLOCKS, 256, GEMM_SMEM>>>(cur16, s16, g16, pinvdeg,
                                                      pWh + l*4*HH, nxt16);
        __half* t16 = cur16; cur16 = nxt16; nxt16 = t16;
    }
    k_head<<<NG + DEGZ_BLOCKS, H>>>(cur16, lro, lout_W, lout_b, cls_W, cls_b,
                                    (float*)d_out);
}